// round 1
// baseline (speedup 1.0000x reference)
#include <cuda_runtime.h>
#include <math.h>

#define NNODES 4096
#define C_MATS 32
#define TOTAL (32 * 4096 * 16)
#define NB 3

// Scratch (no cudaMalloc allowed): per-community causal graphs + per-node class
__device__ float g_graphs[C_MATS * 64];
__device__ int   g_class[NNODES];

// ---------------------------------------------------------------------------
// Complex double helpers
// ---------------------------------------------------------------------------
struct cd { double x, y; };
__device__ __forceinline__ cd cmul(cd a, cd b) { return cd{a.x*b.x - a.y*b.y, a.x*b.y + a.y*b.x}; }
__device__ __forceinline__ cd csub(cd a, cd b) { return cd{a.x - b.x, a.y - b.y}; }
__device__ __forceinline__ cd cdivc(cd a, cd b) {
    double d = b.x*b.x + b.y*b.y;
    return cd{(a.x*b.x + a.y*b.y)/d, (a.y*b.x - a.x*b.y)/d};
}

// ---------------------------------------------------------------------------
// Kernel 1: G[c] = Re( V * (lam*mask) * V^-1 ) computed WITHOUT eigenvectors:
//   G = A * p(A), p = degree-7 polynomial with p(lam_i) = mask_i.
// One block (64 threads) per 8x8 matrix.
//   - char poly: Faddeev-LeVerrier (parallel 8x8 fp64 matmuls in shared)
//   - roots:     Durand-Kerner on lanes 0..7 (warp shuffles, fp64 complex)
//   - mask:      |lam + (1e-10+1e-10i)| in [0.9, 1.1]; if none -> all true
//   - p(A):      Newton divided differences + complex matrix Horner (7 steps)
// ---------------------------------------------------------------------------
__global__ void graphs_kernel(const float* __restrict__ koop)
{
    int c = blockIdx.x;
    int t = threadIdx.x;            // 64 threads
    int i = t >> 3, j = t & 7;

    __shared__ double A[64], M[64], T[64];
    __shared__ double coef[9];      // p(z) = z^8 + coef[1] z^7 + ... + coef[8]
    __shared__ cd zsh[8];           // roots
    __shared__ cd dcoef[8];         // Newton coefficients
    __shared__ cd Mc[64], Tc[64];   // complex matrix Horner buffers

    A[t] = (double)koop[c * 64 + t];
    __syncthreads();

    // Faddeev-LeVerrier
    if (t == 0) { double tr = 0; for (int d = 0; d < 8; d++) tr += A[d * 9]; coef[1] = -tr; }
    M[t] = A[t];
    __syncthreads();
    for (int k = 2; k <= 8; k++) {
        T[t] = M[t] + ((i == j) ? coef[k - 1] : 0.0);
        __syncthreads();
        double s = 0;
        #pragma unroll
        for (int d = 0; d < 8; d++) s += A[i * 8 + d] * T[d * 8 + j];
        M[t] = s;
        __syncthreads();
        if (t == 0) { double tr = 0; for (int d = 0; d < 8; d++) tr += M[d * 9]; coef[k] = -tr / (double)k; }
        __syncthreads();
    }

    // Durand-Kerner root finding (lanes 0..7)
    if (t < 8) {
        cd z = cd{1.0, 0.0};
        cd base = cd{0.4, 0.9};
        for (int p = 0; p <= t; p++) z = cmul(z, base);   // z = base^(t+1)
        const unsigned msk = 0xFFu;
        for (int iter = 0; iter < 300; iter++) {
            cd p = cd{1.0, 0.0};
            #pragma unroll
            for (int k = 1; k <= 8; k++) { p = cmul(p, z); p.x += coef[k]; }
            cd den = cd{1.0, 0.0};
            #pragma unroll
            for (int j2 = 0; j2 < 8; j2++) {
                double zx = __shfl_sync(msk, z.x, j2);
                double zy = __shfl_sync(msk, z.y, j2);
                if (j2 != t) den = cmul(den, csub(z, cd{zx, zy}));
            }
            cd corr = cdivc(p, den);
            z = csub(z, corr);
            double cn = corr.x * corr.x + corr.y * corr.y;
            unsigned done = __ballot_sync(msk, cn < 1e-26);
            if (done == 0xFFu) break;
        }
        zsh[t] = z;
    }
    __syncthreads();

    // Mask + Newton divided differences (tiny; single thread)
    if (t == 0) {
        double m[8]; int any = 0;
        for (int r = 0; r < 8; r++) {
            double zx = zsh[r].x + 1e-10, zy = zsh[r].y + 1e-10;
            double a = sqrt(zx * zx + zy * zy);
            m[r] = (a <= 1.1 && a >= 0.9) ? 1.0 : 0.0;
            if (m[r] != 0.0) any = 1;
        }
        if (!any) for (int r = 0; r < 8; r++) m[r] = 1.0;
        cd f[8];
        for (int r = 0; r < 8; r++) f[r] = cd{m[r], 0.0};
        for (int lev = 1; lev < 8; lev++)
            for (int r = 7; r >= lev; r--)
                f[r] = cdivc(csub(f[r], f[r - 1]), csub(zsh[r], zsh[r - lev]));
        for (int r = 0; r < 8; r++) dcoef[r] = f[r];
    }
    __syncthreads();

    // Matrix Horner: P = d7*I; for k=6..0: P = (A - z_k I) P + d_k I
    Mc[t] = (i == j) ? dcoef[7] : cd{0.0, 0.0};
    __syncthreads();
    for (int k = 6; k >= 0; k--) {
        cd s = cd{0.0, 0.0};
        #pragma unroll
        for (int d = 0; d < 8; d++) { double a = A[i * 8 + d]; cd mm = Mc[d * 8 + j]; s.x += a * mm.x; s.y += a * mm.y; }
        cd zk = zsh[k]; cd mij = Mc[t];
        s.x -= zk.x * mij.x - zk.y * mij.y;
        s.y -= zk.x * mij.y + zk.y * mij.x;
        if (i == j) { s.x += dcoef[k].x; s.y += dcoef[k].y; }
        Tc[t] = s;
        __syncthreads();
        Mc[t] = Tc[t];
        __syncthreads();
    }

    // G = A * Re(P)
    double g = 0;
    #pragma unroll
    for (int d = 0; d < 8; d++) g += A[i * 8 + d] * Mc[d * 8 + j].x;
    g_graphs[c * 64 + t] = (float)g;
}

// ---------------------------------------------------------------------------
// Kernel 2: per-node community argmax (first-max, matching jnp.argmax)
// ---------------------------------------------------------------------------
__global__ void class_kernel(const float* __restrict__ community)
{
    int n = blockIdx.x * blockDim.x + threadIdx.x;
    if (n >= NNODES) return;
    const float* r = community + n * 32;
    float best = r[0]; int bi = 0;
    #pragma unroll
    for (int cc = 1; cc < 32; cc++) { float v = r[cc]; if (v > best) { best = v; bi = cc; } }
    g_class[n] = bi;
}

// ---------------------------------------------------------------------------
// Kernel 3: main fused pass — one row (b,n,t) per thread.
//   cond = x @ G_node;  3 coupling blocks (12->64->64->8 MLP, relu, tanh/exp
//   affine update); log_pz = -0.5*sum(z^2) - c + logdet.
// All weights + G matrices staged in dynamic shared (broadcast LDS.128 reads).
// ---------------------------------------------------------------------------
__global__ void __launch_bounds__(256) prior_kernel(
    const float* __restrict__ latent,
    const float* __restrict__ W0, const float* __restrict__ b0,
    const float* __restrict__ W1, const float* __restrict__ b1,
    const float* __restrict__ W2, const float* __restrict__ b2,
    float* __restrict__ out)
{
    extern __shared__ float smem[];
    float* sW0 = smem;               // 3*12*64  = 2304
    float* sW1 = sW0 + 2304;         // 3*64*64  = 12288
    float* sW2 = sW1 + 12288;        // 3*64*8   = 1536
    float* sb0 = sW2 + 1536;         // 192
    float* sb1 = sb0 + 192;          // 192
    float* sb2 = sb1 + 192;          // 24
    float* sG  = sb2 + 24;           // 32*64    = 2048
    const int tid = threadIdx.x;

    for (int idx = tid; idx < 2304;  idx += 256) sW0[idx] = W0[idx];
    for (int idx = tid; idx < 12288; idx += 256) sW1[idx] = W1[idx];
    for (int idx = tid; idx < 1536;  idx += 256) sW2[idx] = W2[idx];
    if (tid < 192) sb0[tid] = b0[tid];
    if (tid < 192) sb1[tid] = b1[tid];
    if (tid < 24)  sb2[tid] = b2[tid];
    for (int idx = tid; idx < 2048;  idx += 256) sG[idx] = g_graphs[idx];
    __syncthreads();

    const int row = blockIdx.x * 256 + tid;
    const int n = (row >> 4) & (NNODES - 1);
    const float* Gm = sG + g_class[n] * 64;

    const float4* lp = (const float4*)(latent + (size_t)row * 8);
    float4 xa = lp[0];   // x[0:4]
    float4 xb = lp[1];   // x[4:8]

    // cond = x @ G  (from ORIGINAL latent; constant across coupling blocks)
    float cond[8];
    {
        #pragma unroll
        for (int e = 0; e < 8; e++) cond[e] = 0.f;
        float xd[8] = {xa.x, xa.y, xa.z, xa.w, xb.x, xb.y, xb.z, xb.w};
        #pragma unroll
        for (int d = 0; d < 8; d++) {
            const float4* gr = (const float4*)(Gm + d * 8);
            float4 g0 = gr[0], g1 = gr[1];
            cond[0] += xd[d] * g0.x; cond[1] += xd[d] * g0.y;
            cond[2] += xd[d] * g0.z; cond[3] += xd[d] * g0.w;
            cond[4] += xd[d] * g1.x; cond[5] += xd[d] * g1.y;
            cond[6] += xd[d] * g1.z; cond[7] += xd[d] * g1.w;
        }
    }

    float logdet = 0.f;
    for (int blk = 0; blk < NB; blk++) {           // runtime loop: keeps SASS body 1x
        const float* w0 = sW0 + blk * 768;
        const float* w1 = sW1 + blk * 4096;
        const float* w2 = sW2 + blk * 512;
        const bool odd = (blk == 1);
        const float in0 = odd ? xb.x : xa.x;
        const float in1 = odd ? xb.y : xa.y;
        const float in2 = odd ? xb.z : xa.z;
        const float in3 = odd ? xb.w : xa.w;

        // layer 0: [x1(4), cond(8)] @ W0 + b0, relu
        float h[64];
        {
            const float4* bb = (const float4*)(sb0 + blk * 64);
            #pragma unroll
            for (int q = 0; q < 16; q++) { float4 v = bb[q]; h[4*q]=v.x; h[4*q+1]=v.y; h[4*q+2]=v.z; h[4*q+3]=v.w; }
        }
        #pragma unroll
        for (int k = 0; k < 12; k++) {
            float xv;
            if      (k == 0) xv = in0;
            else if (k == 1) xv = in1;
            else if (k == 2) xv = in2;
            else if (k == 3) xv = in3;
            else             xv = cond[k - 4];
            const float4* wr = (const float4*)(w0 + k * 64);
            #pragma unroll
            for (int q = 0; q < 16; q++) { float4 w = wr[q]; h[4*q]+=xv*w.x; h[4*q+1]+=xv*w.y; h[4*q+2]+=xv*w.z; h[4*q+3]+=xv*w.w; }
        }
        #pragma unroll
        for (int q = 0; q < 64; q++) h[q] = fmaxf(h[q], 0.f);

        // layer 1: 64x64, relu
        float h2[64];
        {
            const float4* bb = (const float4*)(sb1 + blk * 64);
            #pragma unroll
            for (int q = 0; q < 16; q++) { float4 v = bb[q]; h2[4*q]=v.x; h2[4*q+1]=v.y; h2[4*q+2]=v.z; h2[4*q+3]=v.w; }
        }
        #pragma unroll
        for (int k = 0; k < 64; k++) {
            float hk = h[k];
            const float4* wr = (const float4*)(w1 + k * 64);
            #pragma unroll
            for (int q = 0; q < 16; q++) { float4 w = wr[q]; h2[4*q]+=hk*w.x; h2[4*q+1]+=hk*w.y; h2[4*q+2]+=hk*w.z; h2[4*q+3]+=hk*w.w; }
        }
        #pragma unroll
        for (int q = 0; q < 64; q++) h2[q] = fmaxf(h2[q], 0.f);

        // layer 2: 64x8
        float o[8];
        {
            const float4* bb = (const float4*)(sb2 + blk * 8);
            float4 v0 = bb[0], v1 = bb[1];
            o[0]=v0.x; o[1]=v0.y; o[2]=v0.z; o[3]=v0.w; o[4]=v1.x; o[5]=v1.y; o[6]=v1.z; o[7]=v1.w;
        }
        #pragma unroll
        for (int k = 0; k < 64; k++) {
            float hk = h2[k];
            const float4* wr = (const float4*)(w2 + k * 8);
            float4 wv0 = wr[0], wv1 = wr[1];
            o[0]+=hk*wv0.x; o[1]+=hk*wv0.y; o[2]+=hk*wv0.z; o[3]+=hk*wv0.w;
            o[4]+=hk*wv1.x; o[5]+=hk*wv1.y; o[6]+=hk*wv1.z; o[7]+=hk*wv1.w;
        }

        // affine update of x2 (= xb normally, xa on the odd block)
        float s0 = tanhf(o[0]), s1 = tanhf(o[1]), s2 = tanhf(o[2]), s3 = tanhf(o[3]);
        logdet += s0 + s1 + s2 + s3;
        float e0 = expf(s0), e1 = expf(s1), e2 = expf(s2), e3 = expf(s3);
        if (odd) {
            xa.x = xa.x*e0 + o[4]; xa.y = xa.y*e1 + o[5]; xa.z = xa.z*e2 + o[6]; xa.w = xa.w*e3 + o[7];
        } else {
            xb.x = xb.x*e0 + o[4]; xb.y = xb.y*e1 + o[5]; xb.z = xb.z*e2 + o[6]; xb.w = xb.w*e3 + o[7];
        }
    }

    float ss = xa.x*xa.x + xa.y*xa.y + xa.z*xa.z + xa.w*xa.w
             + xb.x*xb.x + xb.y*xb.y + xb.z*xb.z + xb.w*xb.w;
    // c = 0.5 * D * ln(2*pi), D = 8
    out[row] = -0.5f * ss - 7.3515082656373815f + logdet;
}

// ---------------------------------------------------------------------------
extern "C" void kernel_launch(void* const* d_in, const int* in_sizes, int n_in,
                              void* d_out, int out_size)
{
    const float* latent    = (const float*)d_in[0];
    const float* koop      = (const float*)d_in[1];
    const float* community = (const float*)d_in[2];
    const float* W0 = (const float*)d_in[3];
    const float* b0 = (const float*)d_in[4];
    const float* W1 = (const float*)d_in[5];
    const float* b1 = (const float*)d_in[6];
    const float* W2 = (const float*)d_in[7];
    const float* b2 = (const float*)d_in[8];
    float* out = (float*)d_out;

    constexpr int SMEM_BYTES = 18584 * (int)sizeof(float);   // 74336 B
    cudaFuncSetAttribute(prior_kernel, cudaFuncAttributeMaxDynamicSharedMemorySize, SMEM_BYTES);

    graphs_kernel<<<C_MATS, 64>>>(koop);
    class_kernel<<<32, 128>>>(community);
    prior_kernel<<<TOTAL / 256, 256, SMEM_BYTES>>>(latent, W0, b0, W1, b1, W2, b2, out);
}

// round 3
// speedup vs baseline: 1.0731x; 1.0731x over previous
#include <cuda_runtime.h>
#include <math.h>

#define NNODES 4096
#define C_MATS 32
#define TOTAL (32 * 4096 * 16)
#define NB 3

typedef unsigned long long u64;

// Scratch (no cudaMalloc allowed): per-community causal graphs + per-node class
__device__ float g_graphs[C_MATS * 64];
__device__ int   g_class[NNODES];

// ---------------------------------------------------------------------------
// Packed f32x2 helpers (sm_100+): 2 IEEE fp32 FMAs per issued instruction.
// ptxas will not auto-fuse these from C++ — must come from PTX.
// ---------------------------------------------------------------------------
__device__ __forceinline__ u64 ffma2(u64 a, u64 b, u64 c) {
    u64 d;
    asm("fma.rn.f32x2 %0, %1, %2, %3;" : "=l"(d) : "l"(a), "l"(b), "l"(c));
    return d;
}
__device__ __forceinline__ u64 pack2(float lo, float hi) {
    u64 r;
    asm("mov.b64 %0, {%1, %2};" : "=l"(r) : "f"(lo), "f"(hi));
    return r;
}
__device__ __forceinline__ void unpack2(u64 v, float& lo, float& hi) {
    asm("mov.b64 {%0, %1}, %2;" : "=f"(lo), "=f"(hi) : "l"(v));
}
// fast tanh via MUFU exp (error ~1e-6, far under the 1e-3 gate)
__device__ __forceinline__ float ftanh(float x) {
    float e = __expf(2.0f * x);
    return __fdividef(e - 1.0f, e + 1.0f);
}

// ---------------------------------------------------------------------------
// Complex double helpers
// ---------------------------------------------------------------------------
struct cd { double x, y; };
__device__ __forceinline__ cd cmul(cd a, cd b) { return cd{a.x*b.x - a.y*b.y, a.x*b.y + a.y*b.x}; }
__device__ __forceinline__ cd csub(cd a, cd b) { return cd{a.x - b.x, a.y - b.y}; }
__device__ __forceinline__ cd cdivc(cd a, cd b) {
    double d = b.x*b.x + b.y*b.y;
    return cd{(a.x*b.x + a.y*b.y)/d, (a.y*b.x - a.x*b.y)/d};
}

// ---------------------------------------------------------------------------
// Kernel 1: G[c] = A * p(A), p = degree-7 polynomial with p(lam_i) = mask_i.
// (eigenvector-free; fp64; one 64-thread block per 8x8 matrix)
// ---------------------------------------------------------------------------
__global__ void __launch_bounds__(64) graphs_kernel(const float* __restrict__ koop)
{
    int c = blockIdx.x;
    int t = threadIdx.x;            // 64 threads
    int i = t >> 3, j = t & 7;

    __shared__ double A[64], M[64], T[64];
    __shared__ double coef[9];
    __shared__ cd zsh[8];
    __shared__ cd dcoef[8];
    __shared__ cd Mc[64], Tc[64];

    A[t] = (double)koop[c * 64 + t];
    __syncthreads();

    // Faddeev-LeVerrier char poly
    if (t == 0) { double tr = 0; for (int d = 0; d < 8; d++) tr += A[d * 9]; coef[1] = -tr; }
    M[t] = A[t];
    __syncthreads();
    for (int k = 2; k <= 8; k++) {
        T[t] = M[t] + ((i == j) ? coef[k - 1] : 0.0);
        __syncthreads();
        double s = 0;
        #pragma unroll
        for (int d = 0; d < 8; d++) s += A[i * 8 + d] * T[d * 8 + j];
        M[t] = s;
        __syncthreads();
        if (t == 0) { double tr = 0; for (int d = 0; d < 8; d++) tr += M[d * 9]; coef[k] = -tr / (double)k; }
        __syncthreads();
    }

    // Durand-Kerner roots (lanes 0..7)
    if (t < 8) {
        cd z = cd{1.0, 0.0};
        cd base = cd{0.4, 0.9};
        for (int p = 0; p <= t; p++) z = cmul(z, base);
        const unsigned msk = 0xFFu;
        for (int iter = 0; iter < 300; iter++) {
            cd p = cd{1.0, 0.0};
            #pragma unroll
            for (int k = 1; k <= 8; k++) { p = cmul(p, z); p.x += coef[k]; }
            cd den = cd{1.0, 0.0};
            #pragma unroll
            for (int j2 = 0; j2 < 8; j2++) {
                double zx = __shfl_sync(msk, z.x, j2);
                double zy = __shfl_sync(msk, z.y, j2);
                if (j2 != t) den = cmul(den, csub(z, cd{zx, zy}));
            }
            cd corr = cdivc(p, den);
            z = csub(z, corr);
            double cn = corr.x * corr.x + corr.y * corr.y;
            unsigned done = __ballot_sync(msk, cn < 1e-26);
            if (done == 0xFFu) break;
        }
        zsh[t] = z;
    }
    __syncthreads();

    // Mask + Newton divided differences
    if (t == 0) {
        double m[8]; int any = 0;
        for (int r = 0; r < 8; r++) {
            double zx = zsh[r].x + 1e-10, zy = zsh[r].y + 1e-10;
            double a = sqrt(zx * zx + zy * zy);
            m[r] = (a <= 1.1 && a >= 0.9) ? 1.0 : 0.0;
            if (m[r] != 0.0) any = 1;
        }
        if (!any) for (int r = 0; r < 8; r++) m[r] = 1.0;
        cd f[8];
        for (int r = 0; r < 8; r++) f[r] = cd{m[r], 0.0};
        for (int lev = 1; lev < 8; lev++)
            for (int r = 7; r >= lev; r--)
                f[r] = cdivc(csub(f[r], f[r - 1]), csub(zsh[r], zsh[r - lev]));
        for (int r = 0; r < 8; r++) dcoef[r] = f[r];
    }
    __syncthreads();

    // Matrix Horner: P = d7*I; for k=6..0: P = (A - z_k I) P + d_k I
    Mc[t] = (i == j) ? dcoef[7] : cd{0.0, 0.0};
    __syncthreads();
    for (int k = 6; k >= 0; k--) {
        cd s = cd{0.0, 0.0};
        #pragma unroll
        for (int d = 0; d < 8; d++) { double a = A[i * 8 + d]; cd mm = Mc[d * 8 + j]; s.x += a * mm.x; s.y += a * mm.y; }
        cd zk = zsh[k]; cd mij = Mc[t];
        s.x -= zk.x * mij.x - zk.y * mij.y;
        s.y -= zk.x * mij.y + zk.y * mij.x;
        if (i == j) { s.x += dcoef[k].x; s.y += dcoef[k].y; }
        Tc[t] = s;
        __syncthreads();
        Mc[t] = Tc[t];
        __syncthreads();
    }

    double g = 0;
    #pragma unroll
    for (int d = 0; d < 8; d++) g += A[i * 8 + d] * Mc[d * 8 + j].x;
    g_graphs[c * 64 + t] = (float)g;
}

// ---------------------------------------------------------------------------
// Kernel 2: per-node community argmax (first-max, matching jnp.argmax)
// ---------------------------------------------------------------------------
__global__ void __launch_bounds__(128) class_kernel(const float* __restrict__ community)
{
    int n = blockIdx.x * blockDim.x + threadIdx.x;
    if (n >= NNODES) return;
    const float* r = community + n * 32;
    float best = r[0]; int bi = 0;
    #pragma unroll
    for (int cc = 1; cc < 32; cc++) { float v = r[cc]; if (v > best) { best = v; bi = cc; } }
    g_class[n] = bi;
}

// ---------------------------------------------------------------------------
// Kernel 3: main fused pass — one row per thread, all GEMV accumulation done
// with packed fma.rn.f32x2 (FFMA2): 2 fp32 MACs per issued instruction.
// ---------------------------------------------------------------------------
__global__ void __launch_bounds__(256) prior_kernel(
    const float* __restrict__ latent,
    const float* __restrict__ W0, const float* __restrict__ b0,
    const float* __restrict__ W1, const float* __restrict__ b1,
    const float* __restrict__ W2, const float* __restrict__ b2,
    float* __restrict__ out)
{
    extern __shared__ float smem[];
    float* sW0 = smem;               // 3*12*64  = 2304
    float* sW1 = sW0 + 2304;         // 3*64*64  = 12288
    float* sW2 = sW1 + 12288;        // 3*64*8   = 1536
    float* sb0 = sW2 + 1536;         // 192
    float* sb1 = sb0 + 192;          // 192
    float* sb2 = sb1 + 192;          // 24
    float* sG  = sb2 + 24;           // 32*64    = 2048
    const int tid = threadIdx.x;

    for (int idx = tid; idx < 2304;  idx += 256) sW0[idx] = W0[idx];
    for (int idx = tid; idx < 12288; idx += 256) sW1[idx] = W1[idx];
    for (int idx = tid; idx < 1536;  idx += 256) sW2[idx] = W2[idx];
    if (tid < 192) sb0[tid] = b0[tid];
    if (tid < 192) sb1[tid] = b1[tid];
    if (tid < 24)  sb2[tid] = b2[tid];
    for (int idx = tid; idx < 2048;  idx += 256) sG[idx] = g_graphs[idx];
    __syncthreads();

    const int row = blockIdx.x * 256 + tid;
    const int n = (row >> 4) & (NNODES - 1);
    const float* Gm = sG + g_class[n] * 64;

    const float4* lp = (const float4*)(latent + (size_t)row * 8);
    float4 xa = lp[0];   // x[0:4]
    float4 xb = lp[1];   // x[4:8]

    // cond = x @ G (packed accumulation)
    float cond[8];
    {
        u64 cA[4];
        const u64 z = pack2(0.f, 0.f);
        cA[0] = z; cA[1] = z; cA[2] = z; cA[3] = z;
        float xd[8] = {xa.x, xa.y, xa.z, xa.w, xb.x, xb.y, xb.z, xb.w};
        #pragma unroll
        for (int d = 0; d < 8; d++) {
            u64 xv2 = pack2(xd[d], xd[d]);
            const ulonglong2* gr = (const ulonglong2*)(Gm + d * 8);
            ulonglong2 g0 = gr[0], g1 = gr[1];
            cA[0] = ffma2(xv2, g0.x, cA[0]);
            cA[1] = ffma2(xv2, g0.y, cA[1]);
            cA[2] = ffma2(xv2, g1.x, cA[2]);
            cA[3] = ffma2(xv2, g1.y, cA[3]);
        }
        #pragma unroll
        for (int q = 0; q < 4; q++) unpack2(cA[q], cond[2*q], cond[2*q+1]);
    }

    float logdet = 0.f;
    for (int blk = 0; blk < NB; blk++) {           // runtime loop: keeps SASS body 1x
        const float* w0 = sW0 + blk * 768;
        const float* w1 = sW1 + blk * 4096;
        const float* w2 = sW2 + blk * 512;
        const bool odd = (blk == 1);
        float xin[12];
        xin[0] = odd ? xb.x : xa.x;
        xin[1] = odd ? xb.y : xa.y;
        xin[2] = odd ? xb.z : xa.z;
        xin[3] = odd ? xb.w : xa.w;
        #pragma unroll
        for (int e = 0; e < 8; e++) xin[4 + e] = cond[e];

        // layer 0: [x1(4), cond(8)] @ W0 + b0, relu
        u64 hA[32];
        {
            const ulonglong2* bb = (const ulonglong2*)(sb0 + blk * 64);
            #pragma unroll
            for (int q = 0; q < 16; q++) { ulonglong2 v = bb[q]; hA[2*q] = v.x; hA[2*q+1] = v.y; }
        }
        #pragma unroll
        for (int k = 0; k < 12; k++) {
            u64 xv2 = pack2(xin[k], xin[k]);
            const ulonglong2* wr = (const ulonglong2*)(w0 + k * 64);
            #pragma unroll
            for (int q = 0; q < 16; q++) {
                ulonglong2 w = wr[q];
                hA[2*q]   = ffma2(xv2, w.x, hA[2*q]);
                hA[2*q+1] = ffma2(xv2, w.y, hA[2*q+1]);
            }
        }
        float h[64];
        #pragma unroll
        for (int q = 0; q < 32; q++) {
            float lo, hi; unpack2(hA[q], lo, hi);
            h[2*q] = fmaxf(lo, 0.f); h[2*q+1] = fmaxf(hi, 0.f);
        }

        // layer 1: 64x64, relu
        u64 h2A[32];
        {
            const ulonglong2* bb = (const ulonglong2*)(sb1 + blk * 64);
            #pragma unroll
            for (int q = 0; q < 16; q++) { ulonglong2 v = bb[q]; h2A[2*q] = v.x; h2A[2*q+1] = v.y; }
        }
        #pragma unroll
        for (int k = 0; k < 64; k++) {
            u64 xv2 = pack2(h[k], h[k]);
            const ulonglong2* wr = (const ulonglong2*)(w1 + k * 64);
            #pragma unroll
            for (int q = 0; q < 16; q++) {
                ulonglong2 w = wr[q];
                h2A[2*q]   = ffma2(xv2, w.x, h2A[2*q]);
                h2A[2*q+1] = ffma2(xv2, w.y, h2A[2*q+1]);
            }
        }
        float h2[64];
        #pragma unroll
        for (int q = 0; q < 32; q++) {
            float lo, hi; unpack2(h2A[q], lo, hi);
            h2[2*q] = fmaxf(lo, 0.f); h2[2*q+1] = fmaxf(hi, 0.f);
        }

        // layer 2: 64x8
        u64 oA[4];
        {
            const ulonglong2* bb = (const ulonglong2*)(sb2 + blk * 8);
            ulonglong2 v0 = bb[0], v1 = bb[1];
            oA[0] = v0.x; oA[1] = v0.y; oA[2] = v1.x; oA[3] = v1.y;
        }
        #pragma unroll
        for (int k = 0; k < 64; k++) {
            u64 xv2 = pack2(h2[k], h2[k]);
            const ulonglong2* wr = (const ulonglong2*)(w2 + k * 8);
            ulonglong2 w0v = wr[0];
            oA[0] = ffma2(xv2, w0v.x, oA[0]);
            oA[1] = ffma2(xv2, w0v.y, oA[1]);
            ulonglong2 w1v = wr[1];
            oA[2] = ffma2(xv2, w1v.x, oA[2]);
            oA[3] = ffma2(xv2, w1v.y, oA[3]);
        }
        float o[8];
        #pragma unroll
        for (int q = 0; q < 4; q++) unpack2(oA[q], o[2*q], o[2*q+1]);

        // affine update of x2 (= xb normally, xa on the odd block)
        float s0 = ftanh(o[0]), s1 = ftanh(o[1]), s2 = ftanh(o[2]), s3 = ftanh(o[3]);
        logdet += s0 + s1 + s2 + s3;
        float e0 = __expf(s0), e1 = __expf(s1), e2 = __expf(s2), e3 = __expf(s3);
        if (odd) {
            xa.x = xa.x*e0 + o[4]; xa.y = xa.y*e1 + o[5]; xa.z = xa.z*e2 + o[6]; xa.w = xa.w*e3 + o[7];
        } else {
            xb.x = xb.x*e0 + o[4]; xb.y = xb.y*e1 + o[5]; xb.z = xb.z*e2 + o[6]; xb.w = xb.w*e3 + o[7];
        }
    }

    float ss = xa.x*xa.x + xa.y*xa.y + xa.z*xa.z + xa.w*xa.w
             + xb.x*xb.x + xb.y*xb.y + xb.z*xb.z + xb.w*xb.w;
    out[row] = -0.5f * ss - 7.3515082656373815f + logdet;
}

// ---------------------------------------------------------------------------
extern "C" void kernel_launch(void* const* d_in, const int* in_sizes, int n_in,
                              void* d_out, int out_size)
{
    const float* latent    = (const float*)d_in[0];
    const float* koop      = (const float*)d_in[1];
    const float* community = (const float*)d_in[2];
    const float* W0 = (const float*)d_in[3];
    const float* b0 = (const float*)d_in[4];
    const float* W1 = (const float*)d_in[5];
    const float* b1 = (const float*)d_in[6];
    const float* W2 = (const float*)d_in[7];
    const float* b2 = (const float*)d_in[8];
    float* out = (float*)d_out;

    constexpr int SMEM_BYTES = 18584 * (int)sizeof(float);   // 74336 B
    cudaFuncSetAttribute(prior_kernel, cudaFuncAttributeMaxDynamicSharedMemorySize, SMEM_BYTES);

    graphs_kernel<<<C_MATS, 64>>>(koop);
    class_kernel<<<32, 128>>>(community);
    prior_kernel<<<TOTAL / 256, 256, SMEM_BYTES>>>(latent, W0, b0, W1, b1, W2, b2, out);
}

// round 5
// speedup vs baseline: 3.5682x; 3.3252x over previous
#include <cuda_runtime.h>
#include <math.h>
#include <stdint.h>

#define NNODES 4096
#define C_MATS 32
#define TOTAL (32 * 4096 * 16)
#define NB 3
#define WARPS 8
#define ITERS 8
#define NCTA (TOTAL / (32 * WARPS * ITERS))   // 1024

typedef unsigned int u32;
typedef unsigned long long u64;

// ---------------------------------------------------------------------------
// Device scratch (no cudaMalloc allowed)
// ---------------------------------------------------------------------------
__device__ float g_graphs[C_MATS * 64];
__device__ int   g_class[NNODES];
// Weight fragments in mma.sync B-fragment layout (col-major k16n8), pre-split:
// u64 per (tile, lane) = {b0 = bf16x2(w[k0],w[k0+1]), b1 = bf16x2(w[k0+8],w[k0+9])}
__device__ u64 g_F0[3 * 8 * 2 * 32];       // [blk][nt(8)][term(2)][lane]   K=16,N=64
__device__ u64 g_F1[3 * 4 * 8 * 2 * 32];   // [blk][kc(4)][nt(8)][term][lane] K=64,N=64
__device__ u64 g_F2[3 * 4 * 2 * 32];       // [blk][kc(4)][term][lane]       K=64,N=8

// ---------------------------------------------------------------------------
// helpers
// ---------------------------------------------------------------------------
// cvt pair: result.lo = bf16(a), result.hi = bf16(b)
#define CVT_BF16X2_F32(result, a, b) \
    asm("cvt.rn.satfinite.bf16x2.f32 %0, %1, %2;" : "=r"(result) : "f"(b), "f"(a))

__device__ __forceinline__ void split2(float e, float o, u32& hi, u32& lo) {
    u32 h; CVT_BF16X2_F32(h, e, o);
    float he = __uint_as_float(h << 16);
    float ho = __uint_as_float(h & 0xFFFF0000u);
    float le = e - he, lf = o - ho;
    u32 l; CVT_BF16X2_F32(l, le, lf);
    hi = h; lo = l;
}

__device__ __forceinline__ void frag_split(float w0, float w1, float w2, float w3,
                                           u64& hi, u64& lo) {
    u32 h0; CVT_BF16X2_F32(h0, w0, w1);
    u32 h1; CVT_BF16X2_F32(h1, w2, w3);
    float r0 = w0 - __uint_as_float(h0 << 16);
    float r1 = w1 - __uint_as_float(h0 & 0xFFFF0000u);
    float r2 = w2 - __uint_as_float(h1 << 16);
    float r3 = w3 - __uint_as_float(h1 & 0xFFFF0000u);
    u32 l0; CVT_BF16X2_F32(l0, r0, r1);
    u32 l1; CVT_BF16X2_F32(l1, r2, r3);
    hi = (u64)h0 | ((u64)h1 << 32);
    lo = (u64)l0 | ((u64)l1 << 32);
}

// m16n8k16 bf16 mma, D accumulates in place (fp32)
__device__ __forceinline__ void mma16816(float* d, const u32* a, u32 b0, u32 b1) {
    asm volatile(
        "mma.sync.aligned.m16n8k16.row.col.f32.bf16.bf16.f32 "
        "{%0,%1,%2,%3}, {%4,%5,%6,%7}, {%8,%9}, {%0,%1,%2,%3};"
        : "+f"(d[0]), "+f"(d[1]), "+f"(d[2]), "+f"(d[3])
        : "r"(a[0]), "r"(a[1]), "r"(a[2]), "r"(a[3]), "r"(b0), "r"(b1));
}

__device__ __forceinline__ float ftanh(float x) {
    float e = __expf(2.0f * x);
    return __fdividef(e - 1.0f, e + 1.0f);
}

// ---------------------------------------------------------------------------
// Complex double helpers (eig-free graphs kernel)
// ---------------------------------------------------------------------------
struct cd { double x, y; };
__device__ __forceinline__ cd cmul(cd a, cd b) { return cd{a.x*b.x - a.y*b.y, a.x*b.y + a.y*b.x}; }
__device__ __forceinline__ cd csub(cd a, cd b) { return cd{a.x - b.x, a.y - b.y}; }
__device__ __forceinline__ cd cdivc(cd a, cd b) {
    double d = b.x*b.x + b.y*b.y;
    return cd{(a.x*b.x + a.y*b.y)/d, (a.y*b.x - a.x*b.y)/d};
}

// ---------------------------------------------------------------------------
// Kernel 1: G[c] = A * p(A)  (validated: rel_err 2.4e-6)
// ---------------------------------------------------------------------------
__global__ void __launch_bounds__(64) graphs_kernel(const float* __restrict__ koop)
{
    int c = blockIdx.x;
    int t = threadIdx.x;
    int i = t >> 3, j = t & 7;

    __shared__ double A[64], M[64], T[64];
    __shared__ double coef[9];
    __shared__ cd zsh[8];
    __shared__ cd dcoef[8];
    __shared__ cd Mc[64], Tc[64];

    A[t] = (double)koop[c * 64 + t];
    __syncthreads();

    if (t == 0) { double tr = 0; for (int d = 0; d < 8; d++) tr += A[d * 9]; coef[1] = -tr; }
    M[t] = A[t];
    __syncthreads();
    for (int k = 2; k <= 8; k++) {
        T[t] = M[t] + ((i == j) ? coef[k - 1] : 0.0);
        __syncthreads();
        double s = 0;
        #pragma unroll
        for (int d = 0; d < 8; d++) s += A[i * 8 + d] * T[d * 8 + j];
        M[t] = s;
        __syncthreads();
        if (t == 0) { double tr = 0; for (int d = 0; d < 8; d++) tr += M[d * 9]; coef[k] = -tr / (double)k; }
        __syncthreads();
    }

    if (t < 8) {
        cd z = cd{1.0, 0.0};
        cd base = cd{0.4, 0.9};
        for (int p = 0; p <= t; p++) z = cmul(z, base);
        const unsigned msk = 0xFFu;
        for (int iter = 0; iter < 300; iter++) {
            cd p = cd{1.0, 0.0};
            #pragma unroll
            for (int k = 1; k <= 8; k++) { p = cmul(p, z); p.x += coef[k]; }
            cd den = cd{1.0, 0.0};
            #pragma unroll
            for (int j2 = 0; j2 < 8; j2++) {
                double zx = __shfl_sync(msk, z.x, j2);
                double zy = __shfl_sync(msk, z.y, j2);
                if (j2 != t) den = cmul(den, csub(z, cd{zx, zy}));
            }
            cd corr = cdivc(p, den);
            z = csub(z, corr);
            double cn = corr.x * corr.x + corr.y * corr.y;
            unsigned done = __ballot_sync(msk, cn < 1e-26);
            if (done == 0xFFu) break;
        }
        zsh[t] = z;
    }
    __syncthreads();

    if (t == 0) {
        double m[8]; int any = 0;
        for (int r = 0; r < 8; r++) {
            double zx = zsh[r].x + 1e-10, zy = zsh[r].y + 1e-10;
            double a = sqrt(zx * zx + zy * zy);
            m[r] = (a <= 1.1 && a >= 0.9) ? 1.0 : 0.0;
            if (m[r] != 0.0) any = 1;
        }
        if (!any) for (int r = 0; r < 8; r++) m[r] = 1.0;
        cd f[8];
        for (int r = 0; r < 8; r++) f[r] = cd{m[r], 0.0};
        for (int lev = 1; lev < 8; lev++)
            for (int r = 7; r >= lev; r--)
                f[r] = cdivc(csub(f[r], f[r - 1]), csub(zsh[r], zsh[r - lev]));
        for (int r = 0; r < 8; r++) dcoef[r] = f[r];
    }
    __syncthreads();

    Mc[t] = (i == j) ? dcoef[7] : cd{0.0, 0.0};
    __syncthreads();
    for (int k = 6; k >= 0; k--) {
        cd s = cd{0.0, 0.0};
        #pragma unroll
        for (int d = 0; d < 8; d++) { double a = A[i * 8 + d]; cd mm = Mc[d * 8 + j]; s.x += a * mm.x; s.y += a * mm.y; }
        cd zk = zsh[k]; cd mij = Mc[t];
        s.x -= zk.x * mij.x - zk.y * mij.y;
        s.y -= zk.x * mij.y + zk.y * mij.x;
        if (i == j) { s.x += dcoef[k].x; s.y += dcoef[k].y; }
        Tc[t] = s;
        __syncthreads();
        Mc[t] = Tc[t];
        __syncthreads();
    }

    double g = 0;
    #pragma unroll
    for (int d = 0; d < 8; d++) g += A[i * 8 + d] * Mc[d * 8 + j].x;
    g_graphs[c * 64 + t] = (float)g;
}

// ---------------------------------------------------------------------------
// Kernel 2: per-node community argmax
// ---------------------------------------------------------------------------
__global__ void __launch_bounds__(128) class_kernel(const float* __restrict__ community)
{
    int n = blockIdx.x * blockDim.x + threadIdx.x;
    if (n >= NNODES) return;
    const float* r = community + n * 32;
    float best = r[0]; int bi = 0;
    #pragma unroll
    for (int cc = 1; cc < 32; cc++) { float v = r[cc]; if (v > best) { best = v; bi = cc; } }
    g_class[n] = bi;
}

// ---------------------------------------------------------------------------
// Kernel 2b: build bf16 hi/lo weight fragments in mma B-fragment layout.
// W0:[blk][k<12][n64]  W1:[blk][k64][n64]  W2:[blk][k64][n8]
// ---------------------------------------------------------------------------
__global__ void __launch_bounds__(128) prep_kernel(
    const float* __restrict__ W0, const float* __restrict__ W1, const float* __restrict__ W2)
{
    int g = blockIdx.x * blockDim.x + threadIdx.x;
    int stride = gridDim.x * blockDim.x;

    // L0: 3*8*32 = 768 positions (K=16 padded from 12)
    for (int i = g; i < 768; i += stride) {
        int lane = i & 31; int t = i >> 5; int nt = t & 7, blk = t >> 3;
        int k0 = (lane & 3) * 2, n = nt * 8 + (lane >> 2);
        const float* W = W0 + blk * 768;
        float w0 = W[k0 * 64 + n];
        float w1 = W[(k0 + 1) * 64 + n];
        float w2 = (k0 + 8 < 12) ? W[(k0 + 8) * 64 + n] : 0.0f;
        float w3 = (k0 + 9 < 12) ? W[(k0 + 9) * 64 + n] : 0.0f;
        u64 hi, lo; frag_split(w0, w1, w2, w3, hi, lo);
        g_F0[((blk * 8 + nt) * 2 + 0) * 32 + lane] = hi;
        g_F0[((blk * 8 + nt) * 2 + 1) * 32 + lane] = lo;
    }
    // L1: 3*4*8*32 = 3072 positions
    for (int i = g; i < 3072; i += stride) {
        int lane = i & 31; int t = i >> 5; int nt = t & 7; int t2 = t >> 3;
        int kc = t2 & 3, blk = t2 >> 2;
        int k0 = kc * 16 + (lane & 3) * 2, n = nt * 8 + (lane >> 2);
        const float* W = W1 + blk * 4096;
        float w0 = W[k0 * 64 + n];
        float w1 = W[(k0 + 1) * 64 + n];
        float w2 = W[(k0 + 8) * 64 + n];
        float w3 = W[(k0 + 9) * 64 + n];
        u64 hi, lo; frag_split(w0, w1, w2, w3, hi, lo);
        g_F1[(((blk * 4 + kc) * 8 + nt) * 2 + 0) * 32 + lane] = hi;
        g_F1[(((blk * 4 + kc) * 8 + nt) * 2 + 1) * 32 + lane] = lo;
    }
    // L2: 3*4*32 = 384 positions (N=8 exact)
    for (int i = g; i < 384; i += stride) {
        int lane = i & 31; int t = i >> 5; int kc = t & 3, blk = t >> 2;
        int k0 = kc * 16 + (lane & 3) * 2, n = lane >> 2;
        const float* W = W2 + blk * 512;
        float w0 = W[k0 * 8 + n];
        float w1 = W[(k0 + 1) * 8 + n];
        float w2 = W[(k0 + 8) * 8 + n];
        float w3 = W[(k0 + 9) * 8 + n];
        u64 hi, lo; frag_split(w0, w1, w2, w3, hi, lo);
        g_F2[((blk * 4 + kc) * 2 + 0) * 32 + lane] = hi;
        g_F2[((blk * 4 + kc) * 2 + 1) * 32 + lane] = lo;
    }
}

// ---------------------------------------------------------------------------
// Kernel 3: main pass on HMMA (mma.sync m16n8k16 bf16, 3-term split).
// Each warp: 32 rows/iter (two m16 groups sharing B loads); lane == row owner
// for x/cond/output; fragments assembled via tiny per-warp smem scratch.
// D-fragment layout == A-fragment layout => in-register layer chaining.
// ---------------------------------------------------------------------------
// smem layout (bytes)
#define SM_F0    0                        // 12288
#define SM_F1    12288                    // 49152
#define SM_F2    61440                    // 6144
#define SM_BIAS0 67584                    // 768
#define SM_BIAS1 68352                    // 768
#define SM_BIAS2 69120                    // 96 (+pad)
#define SM_G     69248                    // 8192
#define SM_SCR   77440                    // 8 warps * 2560
#define SMEM_TOTAL (SM_SCR + WARPS * 2560)   // 97920

__global__ void __launch_bounds__(256) prior_kernel(
    const float* __restrict__ latent,
    const float* __restrict__ b0, const float* __restrict__ b1, const float* __restrict__ b2,
    float* __restrict__ out)
{
    extern __shared__ char smc[];
    const int tid = threadIdx.x;

    // ---- stage fragments / biases / G into smem ----
    {
        u64* dst0 = (u64*)(smc + SM_F0);
        u64* dst1 = (u64*)(smc + SM_F1);
        u64* dst2 = (u64*)(smc + SM_F2);
        for (int i = tid; i < 1536; i += 256) dst0[i] = g_F0[i];
        for (int i = tid; i < 6144; i += 256) dst1[i] = g_F1[i];
        for (int i = tid; i < 768;  i += 256) dst2[i] = g_F2[i];
        float* sb0 = (float*)(smc + SM_BIAS0);
        float* sb1 = (float*)(smc + SM_BIAS1);
        float* sb2 = (float*)(smc + SM_BIAS2);
        if (tid < 192) sb0[tid] = b0[tid];
        if (tid < 192) sb1[tid] = b1[tid];
        if (tid < 24)  sb2[tid] = b2[tid];
        float* sg = (float*)(smc + SM_G);
        for (int i = tid; i < 2048; i += 256) sg[i] = g_graphs[i];
    }
    __syncthreads();

    const int lane = tid & 31;
    const int wld  = tid >> 5;
    const int qr = lane >> 2;       // row within 8-row half
    const int qc = lane & 3;        // column quad
    char* scr = smc + SM_SCR + wld * 2560;
    char* s_cond = scr;             // 32 rows * 32B
    char* s_x1   = scr + 1024;      // 32 rows * 16B
    char* s_o    = scr + 1536;      // 32 rows * 32B

    for (int it = 0; it < ITERS; it++) {
        const int row = ((blockIdx.x * WARPS + wld) * ITERS + it) * 32 + lane;

        const float4* lp = (const float4*)(latent + (size_t)row * 8);
        float4 xa = lp[0];
        float4 xb = lp[1];

        // cond = x @ G (fp32, G in smem)
        const int cls = g_class[(row >> 4) & (NNODES - 1)];
        const float* Gm = (const float*)(smc + SM_G) + cls * 64;
        float cond[8];
        {
            #pragma unroll
            for (int e = 0; e < 8; e++) cond[e] = 0.f;
            float xd[8] = {xa.x, xa.y, xa.z, xa.w, xb.x, xb.y, xb.z, xb.w};
            #pragma unroll
            for (int d = 0; d < 8; d++) {
                float4 g0 = *(const float4*)(Gm + d * 8);
                float4 g1 = *(const float4*)(Gm + d * 8 + 4);
                cond[0] += xd[d] * g0.x; cond[1] += xd[d] * g0.y;
                cond[2] += xd[d] * g0.z; cond[3] += xd[d] * g0.w;
                cond[4] += xd[d] * g1.x; cond[5] += xd[d] * g1.y;
                cond[6] += xd[d] * g1.z; cond[7] += xd[d] * g1.w;
            }
        }
        *(float4*)(s_cond + lane * 32)      = make_float4(cond[0], cond[1], cond[2], cond[3]);
        *(float4*)(s_cond + lane * 32 + 16) = make_float4(cond[4], cond[5], cond[6], cond[7]);

        float logdet = 0.f;

        for (int blk = 0; blk < NB; blk++) {
            const bool odd = (blk == 1);
            *(float4*)(s_x1 + lane * 16) = odd ? xb : xa;
            __syncwarp();

            // ---- L0 A fragments (K=16: [x1(4), cond(8), pad(4)]) ----
            u32 A0h[2][4], A0l[2][4];
            #pragma unroll
            for (int g = 0; g < 2; g++) {
                int r = g * 16 + qr;
                float2 pa, pb, pc, pd;
                if (qc < 2) {
                    pa = *(const float2*)(s_x1 + r * 16 + qc * 8);
                    pb = *(const float2*)(s_x1 + (r + 8) * 16 + qc * 8);
                    pc = *(const float2*)(s_cond + r * 32 + qc * 8 + 16);
                    pd = *(const float2*)(s_cond + (r + 8) * 32 + qc * 8 + 16);
                } else {
                    pa = *(const float2*)(s_cond + r * 32 + qc * 8 - 16);
                    pb = *(const float2*)(s_cond + (r + 8) * 32 + qc * 8 - 16);
                    pc = make_float2(0.f, 0.f);
                    pd = make_float2(0.f, 0.f);
                }
                split2(pa.x, pa.y, A0h[g][0], A0l[g][0]);
                split2(pb.x, pb.y, A0h[g][1], A0l[g][1]);
                split2(pc.x, pc.y, A0h[g][2], A0l[g][2]);
                split2(pd.x, pd.y, A0h[g][3], A0l[g][3]);
            }

            // ---- L0 mma: D[2][8][4] ----
            float D[2][8][4];
            #pragma unroll
            for (int g = 0; g < 2; g++)
                #pragma unroll
                for (int nt = 0; nt < 8; nt++)
                    #pragma unroll
                    for (int q = 0; q < 4; q++) D[g][nt][q] = 0.f;
            #pragma unroll
            for (int nt = 0; nt < 8; nt++) {
                const char* fp = smc + SM_F0 + (size_t)(((blk * 8 + nt) * 2) * 32 + lane) * 8;
                u64 vh = *(const u64*)fp;
                u64 vl = *(const u64*)(fp + 256);
                u32 bh0 = (u32)vh, bh1 = (u32)(vh >> 32);
                u32 bl0 = (u32)vl, bl1 = (u32)(vl >> 32);
                #pragma unroll
                for (int g = 0; g < 2; g++) {
                    mma16816(D[g][nt], A0h[g], bh0, bh1);
                    mma16816(D[g][nt], A0h[g], bl0, bl1);
                    mma16816(D[g][nt], A0l[g], bh0, bh1);
                }
            }

            // ---- L0 epilogue: h = relu(D+b0) -> A frags (K=64) ----
            u32 Ah[2][16], Al[2][16];
            #pragma unroll
            for (int nt = 0; nt < 8; nt++) {
                float2 bv = *(const float2*)(smc + SM_BIAS0 + blk * 256 + nt * 32 + qc * 8);
                int base = (nt >> 1) * 4 + (nt & 1) * 2;
                #pragma unroll
                for (int g = 0; g < 2; g++) {
                    float v0 = fmaxf(D[g][nt][0] + bv.x, 0.f);
                    float v1 = fmaxf(D[g][nt][1] + bv.y, 0.f);
                    float v2 = fmaxf(D[g][nt][2] + bv.x, 0.f);
                    float v3 = fmaxf(D[g][nt][3] + bv.y, 0.f);
                    split2(v0, v1, Ah[g][base],     Al[g][base]);
                    split2(v2, v3, Ah[g][base + 1], Al[g][base + 1]);
                }
            }

            // ---- L1 mma: K=64 x N=64 ----
            #pragma unroll
            for (int g = 0; g < 2; g++)
                #pragma unroll
                for (int nt = 0; nt < 8; nt++)
                    #pragma unroll
                    for (int q = 0; q < 4; q++) D[g][nt][q] = 0.f;
            #pragma unroll
            for (int kc = 0; kc < 4; kc++) {
                #pragma unroll
                for (int nt = 0; nt < 8; nt++) {
                    const char* fp = smc + SM_F1 +
                        (size_t)((((blk * 4 + kc) * 8 + nt) * 2) * 32 + lane) * 8;
                    u64 vh = *(const u64*)fp;
                    u64 vl = *(const u64*)(fp + 256);
                    u32 bh0 = (u32)vh, bh1 = (u32)(vh >> 32);
                    u32 bl0 = (u32)vl, bl1 = (u32)(vl >> 32);
                    #pragma unroll
                    for (int g = 0; g < 2; g++) {
                        mma16816(D[g][nt], &Ah[g][kc * 4], bh0, bh1);
                        mma16816(D[g][nt], &Ah[g][kc * 4], bl0, bl1);
                        mma16816(D[g][nt], &Al[g][kc * 4], bh0, bh1);
                    }
                }
            }

            // ---- L1 epilogue: h2 = relu(D+b1) -> A frags ----
            #pragma unroll
            for (int nt = 0; nt < 8; nt++) {
                float2 bv = *(const float2*)(smc + SM_BIAS1 + blk * 256 + nt * 32 + qc * 8);
                int base = (nt >> 1) * 4 + (nt & 1) * 2;
                #pragma unroll
                for (int g = 0; g < 2; g++) {
                    float v0 = fmaxf(D[g][nt][0] + bv.x, 0.f);
                    float v1 = fmaxf(D[g][nt][1] + bv.y, 0.f);
                    float v2 = fmaxf(D[g][nt][2] + bv.x, 0.f);
                    float v3 = fmaxf(D[g][nt][3] + bv.y, 0.f);
                    split2(v0, v1, Ah[g][base],     Al[g][base]);
                    split2(v2, v3, Ah[g][base + 1], Al[g][base + 1]);
                }
            }

            // ---- L2 mma: K=64 x N=8 ----
            float O[2][4];
            #pragma unroll
            for (int g = 0; g < 2; g++)
                #pragma unroll
                for (int q = 0; q < 4; q++) O[g][q] = 0.f;
            #pragma unroll
            for (int kc = 0; kc < 4; kc++) {
                const char* fp = smc + SM_F2 +
                    (size_t)(((blk * 4 + kc) * 2) * 32 + lane) * 8;
                u64 vh = *(const u64*)fp;
                u64 vl = *(const u64*)(fp + 256);
                u32 bh0 = (u32)vh, bh1 = (u32)(vh >> 32);
                u32 bl0 = (u32)vl, bl1 = (u32)(vl >> 32);
                #pragma unroll
                for (int g = 0; g < 2; g++) {
                    mma16816(O[g], &Ah[g][kc * 4], bh0, bh1);
                    mma16816(O[g], &Ah[g][kc * 4], bl0, bl1);
                    mma16816(O[g], &Al[g][kc * 4], bh0, bh1);
                }
            }

            // ---- distribute o back to row owners ----
            {
                float2 bv = *(const float2*)(smc + SM_BIAS2 + blk * 32 + qc * 8);
                #pragma unroll
                for (int g = 0; g < 2; g++) {
                    int r = g * 16 + qr;
                    *(float2*)(s_o + r * 32 + qc * 8)       = make_float2(O[g][0] + bv.x, O[g][1] + bv.y);
                    *(float2*)(s_o + (r + 8) * 32 + qc * 8) = make_float2(O[g][2] + bv.x, O[g][3] + bv.y);
                }
            }
            __syncwarp();

            // ---- per-row affine update ----
            {
                float4 oA = *(const float4*)(s_o + lane * 32);
                float4 oB = *(const float4*)(s_o + lane * 32 + 16);
                float s0 = ftanh(oA.x), s1 = ftanh(oA.y), s2 = ftanh(oA.z), s3 = ftanh(oA.w);
                logdet += s0 + s1 + s2 + s3;
                float e0 = __expf(s0), e1 = __expf(s1), e2 = __expf(s2), e3 = __expf(s3);
                if (odd) {
                    xa.x = xa.x*e0 + oB.x; xa.y = xa.y*e1 + oB.y;
                    xa.z = xa.z*e2 + oB.z; xa.w = xa.w*e3 + oB.w;
                } else {
                    xb.x = xb.x*e0 + oB.x; xb.y = xb.y*e1 + oB.y;
                    xb.z = xb.z*e2 + oB.z; xb.w = xb.w*e3 + oB.w;
                }
            }
        }

        float ss = xa.x*xa.x + xa.y*xa.y + xa.z*xa.z + xa.w*xa.w
                 + xb.x*xb.x + xb.y*xb.y + xb.z*xb.z + xb.w*xb.w;
        out[row] = -0.5f * ss - 7.3515082656373815f + logdet;
        __syncwarp();
    }
}

// ---------------------------------------------------------------------------
extern "C" void kernel_launch(void* const* d_in, const int* in_sizes, int n_in,
                              void* d_out, int out_size)
{
    const float* latent    = (const float*)d_in[0];
    const float* koop      = (const float*)d_in[1];
    const float* community = (const float*)d_in[2];
    const float* W0 = (const float*)d_in[3];
    const float* b0 = (const float*)d_in[4];
    const float* W1 = (const float*)d_in[5];
    const float* b1 = (const float*)d_in[6];
    const float* W2 = (const float*)d_in[7];
    const float* b2 = (const float*)d_in[8];
    float* out = (float*)d_out;

    cudaFuncSetAttribute(prior_kernel, cudaFuncAttributeMaxDynamicSharedMemorySize, SMEM_TOTAL);

    graphs_kernel<<<C_MATS, 64>>>(koop);
    class_kernel<<<32, 128>>>(community);
    prep_kernel<<<33, 128>>>(W0, W1, W2);
    prior_kernel<<<NCTA, 256, SMEM_TOTAL>>>(latent, b0, b1, b2, out);
}

// round 7
// speedup vs baseline: 3.7265x; 1.0444x over previous
#include <cuda_runtime.h>
#include <math.h>
#include <stdint.h>

#define NNODES 4096
#define C_MATS 32
#define TOTAL (32 * 4096 * 16)
#define NB 3
#define WARPS 8
#define ITERS 4
#define NCTA (TOTAL / (32 * WARPS * ITERS))   // 2048

typedef unsigned int u32;
typedef unsigned long long u64;

// ---------------------------------------------------------------------------
// Device scratch (no cudaMalloc allowed)
// ---------------------------------------------------------------------------
__device__ float g_graphs[C_MATS * 64];
__device__ int   g_class[NNODES];
// Weight fragments in mma.sync B-fragment layout (col-major k16n8), pre-split:
// u64 per (tile, lane) = {b0 = bf16x2(w[k0],w[k0+1]), b1 = bf16x2(w[k0+8],w[k0+9])}
__device__ u64 g_F0[3 * 8 * 2 * 32];       // [blk][nt(8)][term(2)][lane]   K=16,N=64
__device__ u64 g_F1[3 * 4 * 8 * 2 * 32];   // [blk][kc(4)][nt(8)][term][lane] K=64,N=64
__device__ u64 g_F2[3 * 4 * 2 * 32];       // [blk][kc(4)][term][lane]       K=64,N=8

// ---------------------------------------------------------------------------
// helpers
// ---------------------------------------------------------------------------
#define CVT_BF16X2_F32(result, a, b) \
    asm("cvt.rn.satfinite.bf16x2.f32 %0, %1, %2;" : "=r"(result) : "f"(b), "f"(a))

__device__ __forceinline__ void split2(float e, float o, u32& hi, u32& lo) {
    u32 h; CVT_BF16X2_F32(h, e, o);
    float he = __uint_as_float(h << 16);
    float ho = __uint_as_float(h & 0xFFFF0000u);
    float le = e - he, lf = o - ho;
    u32 l; CVT_BF16X2_F32(l, le, lf);
    hi = h; lo = l;
}

__device__ __forceinline__ void frag_split(float w0, float w1, float w2, float w3,
                                           u64& hi, u64& lo) {
    u32 h0; CVT_BF16X2_F32(h0, w0, w1);
    u32 h1; CVT_BF16X2_F32(h1, w2, w3);
    float r0 = w0 - __uint_as_float(h0 << 16);
    float r1 = w1 - __uint_as_float(h0 & 0xFFFF0000u);
    float r2 = w2 - __uint_as_float(h1 << 16);
    float r3 = w3 - __uint_as_float(h1 & 0xFFFF0000u);
    u32 l0; CVT_BF16X2_F32(l0, r0, r1);
    u32 l1; CVT_BF16X2_F32(l1, r2, r3);
    hi = (u64)h0 | ((u64)h1 << 32);
    lo = (u64)l0 | ((u64)l1 << 32);
}

// m16n8k16 bf16 mma, D accumulates in place (fp32)
__device__ __forceinline__ void mma16816(float* d, const u32* a, u32 b0, u32 b1) {
    asm volatile(
        "mma.sync.aligned.m16n8k16.row.col.f32.bf16.bf16.f32 "
        "{%0,%1,%2,%3}, {%4,%5,%6,%7}, {%8,%9}, {%0,%1,%2,%3};"
        : "+f"(d[0]), "+f"(d[1]), "+f"(d[2]), "+f"(d[3])
        : "r"(a[0]), "r"(a[1]), "r"(a[2]), "r"(a[3]), "r"(b0), "r"(b1));
}

__device__ __forceinline__ float ftanh(float x) {
    float e = __expf(2.0f * x);
    return __fdividef(e - 1.0f, e + 1.0f);
}

// ---------------------------------------------------------------------------
// Complex double helpers (eig-free graphs kernel)
// ---------------------------------------------------------------------------
struct cd { double x, y; };
__device__ __forceinline__ cd cmul(cd a, cd b) { return cd{a.x*b.x - a.y*b.y, a.x*b.y + a.y*b.x}; }
__device__ __forceinline__ cd csub(cd a, cd b) { return cd{a.x - b.x, a.y - b.y}; }
__device__ __forceinline__ cd cdivc(cd a, cd b) {
    double d = b.x*b.x + b.y*b.y;
    return cd{(a.x*b.x + a.y*b.y)/d, (a.y*b.x - a.x*b.y)/d};
}

// ---------------------------------------------------------------------------
// Kernel 1: G[c] = A * p(A)  (validated: rel_err ~2.4e-6)
// ---------------------------------------------------------------------------
__global__ void __launch_bounds__(64) graphs_kernel(const float* __restrict__ koop)
{
    int c = blockIdx.x;
    int t = threadIdx.x;
    int i = t >> 3, j = t & 7;

    __shared__ double A[64], M[64], T[64];
    __shared__ double coef[9];
    __shared__ cd zsh[8];
    __shared__ cd dcoef[8];
    __shared__ cd Mc[64], Tc[64];

    A[t] = (double)koop[c * 64 + t];
    __syncthreads();

    if (t == 0) { double tr = 0; for (int d = 0; d < 8; d++) tr += A[d * 9]; coef[1] = -tr; }
    M[t] = A[t];
    __syncthreads();
    for (int k = 2; k <= 8; k++) {
        T[t] = M[t] + ((i == j) ? coef[k - 1] : 0.0);
        __syncthreads();
        double s = 0;
        #pragma unroll
        for (int d = 0; d < 8; d++) s += A[i * 8 + d] * T[d * 8 + j];
        M[t] = s;
        __syncthreads();
        if (t == 0) { double tr = 0; for (int d = 0; d < 8; d++) tr += M[d * 9]; coef[k] = -tr / (double)k; }
        __syncthreads();
    }

    if (t < 8) {
        cd z = cd{1.0, 0.0};
        cd base = cd{0.4, 0.9};
        for (int p = 0; p <= t; p++) z = cmul(z, base);
        const unsigned msk = 0xFFu;
        for (int iter = 0; iter < 300; iter++) {
            cd p = cd{1.0, 0.0};
            #pragma unroll
            for (int k = 1; k <= 8; k++) { p = cmul(p, z); p.x += coef[k]; }
            cd den = cd{1.0, 0.0};
            #pragma unroll
            for (int j2 = 0; j2 < 8; j2++) {
                double zx = __shfl_sync(msk, z.x, j2);
                double zy = __shfl_sync(msk, z.y, j2);
                if (j2 != t) den = cmul(den, csub(z, cd{zx, zy}));
            }
            cd corr = cdivc(p, den);
            z = csub(z, corr);
            double cn = corr.x * corr.x + corr.y * corr.y;
            unsigned done = __ballot_sync(msk, cn < 1e-26);
            if (done == 0xFFu) break;
        }
        zsh[t] = z;
    }
    __syncthreads();

    if (t == 0) {
        double m[8]; int any = 0;
        for (int r = 0; r < 8; r++) {
            double zx = zsh[r].x + 1e-10, zy = zsh[r].y + 1e-10;
            double a = sqrt(zx * zx + zy * zy);
            m[r] = (a <= 1.1 && a >= 0.9) ? 1.0 : 0.0;
            if (m[r] != 0.0) any = 1;
        }
        if (!any) for (int r = 0; r < 8; r++) m[r] = 1.0;
        cd f[8];
        for (int r = 0; r < 8; r++) f[r] = cd{m[r], 0.0};
        for (int lev = 1; lev < 8; lev++)
            for (int r = 7; r >= lev; r--)
                f[r] = cdivc(csub(f[r], f[r - 1]), csub(zsh[r], zsh[r - lev]));
        for (int r = 0; r < 8; r++) dcoef[r] = f[r];
    }
    __syncthreads();

    Mc[t] = (i == j) ? dcoef[7] : cd{0.0, 0.0};
    __syncthreads();
    for (int k = 6; k >= 0; k--) {
        cd s = cd{0.0, 0.0};
        #pragma unroll
        for (int d = 0; d < 8; d++) { double a = A[i * 8 + d]; cd mm = Mc[d * 8 + j]; s.x += a * mm.x; s.y += a * mm.y; }
        cd zk = zsh[k]; cd mij = Mc[t];
        s.x -= zk.x * mij.x - zk.y * mij.y;
        s.y -= zk.x * mij.y + zk.y * mij.x;
        if (i == j) { s.x += dcoef[k].x; s.y += dcoef[k].y; }
        Tc[t] = s;
        __syncthreads();
        Mc[t] = Tc[t];
        __syncthreads();
    }

    double g = 0;
    #pragma unroll
    for (int d = 0; d < 8; d++) g += A[i * 8 + d] * Mc[d * 8 + j].x;
    g_graphs[c * 64 + t] = (float)g;
}

// ---------------------------------------------------------------------------
// Kernel 2: per-node community argmax
// ---------------------------------------------------------------------------
__global__ void __launch_bounds__(128) class_kernel(const float* __restrict__ community)
{
    int n = blockIdx.x * blockDim.x + threadIdx.x;
    if (n >= NNODES) return;
    const float* r = community + n * 32;
    float best = r[0]; int bi = 0;
    #pragma unroll
    for (int cc = 1; cc < 32; cc++) { float v = r[cc]; if (v > best) { best = v; bi = cc; } }
    g_class[n] = bi;
}

// ---------------------------------------------------------------------------
// Kernel 2b: build bf16 hi/lo weight fragments in mma B-fragment layout.
// ---------------------------------------------------------------------------
__global__ void __launch_bounds__(128) prep_kernel(
    const float* __restrict__ W0, const float* __restrict__ W1, const float* __restrict__ W2)
{
    int g = blockIdx.x * blockDim.x + threadIdx.x;
    int stride = gridDim.x * blockDim.x;

    for (int i = g; i < 768; i += stride) {
        int lane = i & 31; int t = i >> 5; int nt = t & 7, blk = t >> 3;
        int k0 = (lane & 3) * 2, n = nt * 8 + (lane >> 2);
        const float* W = W0 + blk * 768;
        float w0 = W[k0 * 64 + n];
        float w1 = W[(k0 + 1) * 64 + n];
        float w2 = (k0 + 8 < 12) ? W[(k0 + 8) * 64 + n] : 0.0f;
        float w3 = (k0 + 9 < 12) ? W[(k0 + 9) * 64 + n] : 0.0f;
        u64 hi, lo; frag_split(w0, w1, w2, w3, hi, lo);
        g_F0[((blk * 8 + nt) * 2 + 0) * 32 + lane] = hi;
        g_F0[((blk * 8 + nt) * 2 + 1) * 32 + lane] = lo;
    }
    for (int i = g; i < 3072; i += stride) {
        int lane = i & 31; int t = i >> 5; int nt = t & 7; int t2 = t >> 3;
        int kc = t2 & 3, blk = t2 >> 2;
        int k0 = kc * 16 + (lane & 3) * 2, n = nt * 8 + (lane >> 2);
        const float* W = W1 + blk * 4096;
        float w0 = W[k0 * 64 + n];
        float w1 = W[(k0 + 1) * 64 + n];
        float w2 = W[(k0 + 8) * 64 + n];
        float w3 = W[(k0 + 9) * 64 + n];
        u64 hi, lo; frag_split(w0, w1, w2, w3, hi, lo);
        g_F1[(((blk * 4 + kc) * 8 + nt) * 2 + 0) * 32 + lane] = hi;
        g_F1[(((blk * 4 + kc) * 8 + nt) * 2 + 1) * 32 + lane] = lo;
    }
    for (int i = g; i < 384; i += stride) {
        int lane = i & 31; int t = i >> 5; int kc = t & 3, blk = t >> 2;
        int k0 = kc * 16 + (lane & 3) * 2, n = lane >> 2;
        const float* W = W2 + blk * 512;
        float w0 = W[k0 * 8 + n];
        float w1 = W[(k0 + 1) * 8 + n];
        float w2 = W[(k0 + 8) * 8 + n];
        float w3 = W[(k0 + 9) * 8 + n];
        u64 hi, lo; frag_split(w0, w1, w2, w3, hi, lo);
        g_F2[((blk * 4 + kc) * 2 + 0) * 32 + lane] = hi;
        g_F2[((blk * 4 + kc) * 2 + 1) * 32 + lane] = lo;
    }
}

// ---------------------------------------------------------------------------
// Kernel 3: HMMA main pass, single m16 row-group per MMA phase (low regs ->
// 2 CTAs/SM). 32 rows per warp-iter processed as two sequential m16 tiles;
// per-row work (cond/tanh/exp/affine/out) uses all 32 lanes.
// ---------------------------------------------------------------------------
// smem layout (bytes)
#define SM_F0    0                        // 12288
#define SM_F1    12288                    // 49152
#define SM_F2    61440                    // 6144
#define SM_BIAS0 67584                    // 768
#define SM_BIAS1 68352                    // 768
#define SM_BIAS2 69120                    // 96 (+pad)
#define SM_G     69248                    // 8192
#define SM_SCR   77440                    // 8 warps * 2048
#define SMEM_TOTAL (SM_SCR + WARPS * 2048)   // 93824

__global__ void __launch_bounds__(256, 2) prior_kernel(
    const float* __restrict__ latent,
    const float* __restrict__ b0, const float* __restrict__ b1, const float* __restrict__ b2,
    float* __restrict__ out)
{
    extern __shared__ char smc[];
    const int tid = threadIdx.x;

    // ---- stage fragments / biases / G into smem ----
    {
        u64* dst0 = (u64*)(smc + SM_F0);
        u64* dst1 = (u64*)(smc + SM_F1);
        u64* dst2 = (u64*)(smc + SM_F2);
        for (int i = tid; i < 1536; i += 256) dst0[i] = g_F0[i];
        for (int i = tid; i < 6144; i += 256) dst1[i] = g_F1[i];
        for (int i = tid; i < 768;  i += 256) dst2[i] = g_F2[i];
        float* sb0 = (float*)(smc + SM_BIAS0);
        float* sb1 = (float*)(smc + SM_BIAS1);
        float* sb2 = (float*)(smc + SM_BIAS2);
        if (tid < 192) sb0[tid] = b0[tid];
        if (tid < 192) sb1[tid] = b1[tid];
        if (tid < 24)  sb2[tid] = b2[tid];
        float* sg = (float*)(smc + SM_G);
        for (int i = tid; i < 2048; i += 256) sg[i] = g_graphs[i];
    }
    __syncthreads();

    const int lane = tid & 31;
    const int wld  = tid >> 5;
    const int qr = lane >> 2;       // frag row within 8-row half
    const int qc = lane & 3;        // column quad
    char* scr = smc + SM_SCR + wld * 2048;
    char* s_cond = scr;             // 32 rows * 32B = 1024
    char* s_x1   = scr + 1024;      // 16 rows * 16B = 256 (tile-local)
    char* s_o    = scr + 1280;      // 16 rows * 32B = 512 (tile-local)

    // per-lane fragment-table base pointers (hoisted)
    const char* f0l = smc + SM_F0 + (size_t)lane * 8;
    const char* f1l = smc + SM_F1 + (size_t)lane * 8;
    const char* f2l = smc + SM_F2 + (size_t)lane * 8;

    for (int it = 0; it < ITERS; it++) {
        const int row = ((blockIdx.x * WARPS + wld) * ITERS + it) * 32 + lane;

        const float4* lp = (const float4*)(latent + (size_t)row * 8);
        float4 xa = lp[0];
        float4 xb = lp[1];

        // cond = x @ G (fp32, all 32 lanes, own row)
        const int cls = g_class[(row >> 4) & (NNODES - 1)];
        const float* Gm = (const float*)(smc + SM_G) + cls * 64;
        __syncwarp();   // previous iter's frag builds done before overwriting s_cond
        {
            float c0=0.f,c1=0.f,c2=0.f,c3=0.f,c4=0.f,c5=0.f,c6=0.f,c7=0.f;
            float xd[8] = {xa.x, xa.y, xa.z, xa.w, xb.x, xb.y, xb.z, xb.w};
            #pragma unroll
            for (int d = 0; d < 8; d++) {
                float4 g0 = *(const float4*)(Gm + d * 8);
                float4 g1 = *(const float4*)(Gm + d * 8 + 4);
                c0 += xd[d] * g0.x; c1 += xd[d] * g0.y;
                c2 += xd[d] * g0.z; c3 += xd[d] * g0.w;
                c4 += xd[d] * g1.x; c5 += xd[d] * g1.y;
                c6 += xd[d] * g1.z; c7 += xd[d] * g1.w;
            }
            *(float4*)(s_cond + lane * 32)      = make_float4(c0, c1, c2, c3);
            *(float4*)(s_cond + lane * 32 + 16) = make_float4(c4, c5, c6, c7);
        }
        __syncwarp();

        float logdet = 0.f;

        for (int h = 0; h < 2; h++) {
            const bool owner = ((lane >> 4) == h);
            const char* cb = s_cond + h * 512;          // tile's 16 cond rows

            for (int blk = 0; blk < NB; blk++) {
                const bool odd = (blk == 1);
                if (owner) *(float4*)(s_x1 + (lane & 15) * 16) = odd ? xb : xa;
                __syncwarp();

                // ---- L0 A fragments (K=16: [x1(4), cond(8), pad(4)]) ----
                u32 A0h[4], A0l[4];
                {
                    float2 pa, pb, pc, pd;
                    if (qc < 2) {
                        pa = *(const float2*)(s_x1 + qr * 16 + qc * 8);
                        pb = *(const float2*)(s_x1 + (qr + 8) * 16 + qc * 8);
                        pc = *(const float2*)(cb + qr * 32 + qc * 8 + 16);
                        pd = *(const float2*)(cb + (qr + 8) * 32 + qc * 8 + 16);
                    } else {
                        pa = *(const float2*)(cb + qr * 32 + qc * 8 - 16);
                        pb = *(const float2*)(cb + (qr + 8) * 32 + qc * 8 - 16);
                        pc = make_float2(0.f, 0.f);
                        pd = make_float2(0.f, 0.f);
                    }
                    split2(pa.x, pa.y, A0h[0], A0l[0]);
                    split2(pb.x, pb.y, A0h[1], A0l[1]);
                    split2(pc.x, pc.y, A0h[2], A0l[2]);
                    split2(pd.x, pd.y, A0h[3], A0l[3]);
                }

                // ---- L0 mma: D[8][4] ----
                float D[8][4];
                #pragma unroll
                for (int nt = 0; nt < 8; nt++)
                    #pragma unroll
                    for (int q = 0; q < 4; q++) D[nt][q] = 0.f;
                #pragma unroll
                for (int nt = 0; nt < 8; nt++) {
                    const char* fp = f0l + (size_t)(blk * 8 + nt) * 512;
                    u64 vh = *(const u64*)fp;
                    u64 vl = *(const u64*)(fp + 256);
                    mma16816(D[nt], A0h, (u32)vh, (u32)(vh >> 32));
                    mma16816(D[nt], A0h, (u32)vl, (u32)(vl >> 32));
                    mma16816(D[nt], A0l, (u32)vh, (u32)(vh >> 32));
                }

                // ---- L0 epilogue: h1 = relu(D+b0) -> A frags (K=64) ----
                u32 Ah[16], Al[16];
                #pragma unroll
                for (int nt = 0; nt < 8; nt++) {
                    float2 bv = *(const float2*)(smc + SM_BIAS0 + blk * 256 + nt * 32 + qc * 8);
                    int base = (nt >> 1) * 4 + (nt & 1) * 2;
                    float v0 = fmaxf(D[nt][0] + bv.x, 0.f);
                    float v1 = fmaxf(D[nt][1] + bv.y, 0.f);
                    float v2 = fmaxf(D[nt][2] + bv.x, 0.f);
                    float v3 = fmaxf(D[nt][3] + bv.y, 0.f);
                    split2(v0, v1, Ah[base],     Al[base]);
                    split2(v2, v3, Ah[base + 1], Al[base + 1]);
                }

                // ---- L1 mma: K=64 x N=64 ----
                #pragma unroll
                for (int nt = 0; nt < 8; nt++)
                    #pragma unroll
                    for (int q = 0; q < 4; q++) D[nt][q] = 0.f;
                #pragma unroll
                for (int kc = 0; kc < 4; kc++) {
                    #pragma unroll
                    for (int nt = 0; nt < 8; nt++) {
                        const char* fp = f1l + (size_t)((blk * 4 + kc) * 8 + nt) * 512;
                        u64 vh = *(const u64*)fp;
                        u64 vl = *(const u64*)(fp + 256);
                        mma16816(D[nt], &Ah[kc * 4], (u32)vh, (u32)(vh >> 32));
                        mma16816(D[nt], &Ah[kc * 4], (u32)vl, (u32)(vl >> 32));
                        mma16816(D[nt], &Al[kc * 4], (u32)vh, (u32)(vh >> 32));
                    }
                }

                // ---- L1 epilogue ----
                #pragma unroll
                for (int nt = 0; nt < 8; nt++) {
                    float2 bv = *(const float2*)(smc + SM_BIAS1 + blk * 256 + nt * 32 + qc * 8);
                    int base = (nt >> 1) * 4 + (nt & 1) * 2;
                    float v0 = fmaxf(D[nt][0] + bv.x, 0.f);
                    float v1 = fmaxf(D[nt][1] + bv.y, 0.f);
                    float v2 = fmaxf(D[nt][2] + bv.x, 0.f);
                    float v3 = fmaxf(D[nt][3] + bv.y, 0.f);
                    split2(v0, v1, Ah[base],     Al[base]);
                    split2(v2, v3, Ah[base + 1], Al[base + 1]);
                }

                // ---- L2 mma: K=64 x N=8 ----
                float O[4] = {0.f, 0.f, 0.f, 0.f};
                #pragma unroll
                for (int kc = 0; kc < 4; kc++) {
                    const char* fp = f2l + (size_t)(blk * 4 + kc) * 512;
                    u64 vh = *(const u64*)fp;
                    u64 vl = *(const u64*)(fp + 256);
                    mma16816(O, &Ah[kc * 4], (u32)vh, (u32)(vh >> 32));
                    mma16816(O, &Ah[kc * 4], (u32)vl, (u32)(vl >> 32));
                    mma16816(O, &Al[kc * 4], (u32)vh, (u32)(vh >> 32));
                }

                // ---- distribute o to tile rows ----
                {
                    float2 bv = *(const float2*)(smc + SM_BIAS2 + blk * 32 + qc * 8);
                    *(float2*)(s_o + qr * 32 + qc * 8)       = make_float2(O[0] + bv.x, O[1] + bv.y);
                    *(float2*)(s_o + (qr + 8) * 32 + qc * 8) = make_float2(O[2] + bv.x, O[3] + bv.y);
                }
                __syncwarp();

                // ---- per-row affine update (owner lanes) ----
                if (owner) {
                    int r = lane & 15;
                    float4 oA = *(const float4*)(s_o + r * 32);
                    float4 oB = *(const float4*)(s_o + r * 32 + 16);
                    float s0 = ftanh(oA.x), s1 = ftanh(oA.y), s2 = ftanh(oA.z), s3 = ftanh(oA.w);
                    logdet += s0 + s1 + s2 + s3;
                    float e0 = __expf(s0), e1 = __expf(s1), e2 = __expf(s2), e3 = __expf(s3);
                    if (odd) {
                        xa.x = xa.x*e0 + oB.x; xa.y = xa.y*e1 + oB.y;
                        xa.z = xa.z*e2 + oB.z; xa.w = xa.w*e3 + oB.w;
                    } else {
                        xb.x = xb.x*e0 + oB.x; xb.y = xb.y*e1 + oB.y;
                        xb.z = xb.z*e2 + oB.z; xb.w = xb.w*e3 + oB.w;
                    }
                }
                __syncwarp();
            }
        }

        float ss = xa.x*xa.x + xa.y*xa.y + xa.z*xa.z + xa.w*xa.w
                 + xb.x*xb.x + xb.y*xb.y + xb.z*xb.z + xb.w*xb.w;
        out[row] = -0.5f * ss - 7.3515082656373815f + logdet;
    }
}

// ---------------------------------------------------------------------------
extern "C" void kernel_launch(void* const* d_in, const int* in_sizes, int n_in,
                              void* d_out, int out_size)
{
    const float* latent    = (const float*)d_in[0];
    const float* koop      = (const float*)d_in[1];
    const float* community = (const float*)d_in[2];
    const float* W0 = (const float*)d_in[3];
    const float* b0 = (const float*)d_in[4];
    const float* W1 = (const float*)d_in[5];
    const float* b1 = (const float*)d_in[6];
    const float* W2 = (const float*)d_in[7];
    const float* b2 = (const float*)d_in[8];
    float* out = (float*)d_out;

    cudaFuncSetAttribute(prior_kernel, cudaFuncAttributeMaxDynamicSharedMemorySize, SMEM_TOTAL);

    graphs_kernel<<<C_MATS, 64>>>(koop);
    class_kernel<<<32, 128>>>(community);
    prep_kernel<<<33, 128>>>(W0, W1, W2);
    prior_kernel<<<NCTA, 256, SMEM_TOTAL>>>(latent, b0, b1, b2, out);
}